// round 13
// baseline (speedup 1.0000x reference)
#include <cuda_runtime.h>
#include <cuda_bf16.h>
#include <cstddef>
#include <cstdint>

#define N_ROWS 131072
#define K_CODES 1024
#define D_DIM 128
#define TAU 2e-3f    // >= 2x worst-case approx gap-error bound (~1e-3)
#define FLAG_CAP 32768

#define AS_STRIDE_B 528               // A row stride bytes (256 bf16 + 16B pad)
#define SM_TOTAL (128 * AS_STRIDE_B)  // 67584 -> 2 CTAs/SM, 93KB L1D left

// ---- scratch (device-only access) ----
__device__ int   g_idx[N_ROWS];
__device__ float g_enorm[K_CODES];
__device__ float g_cnorm[N_ROWS];
__device__ float g_lossPartial[N_ROWS / 128];
__device__ int   g_flagCount;
__device__ int   g_flagRows[FLAG_CAP];
// B' image: [n][256] bf16 = [b1(128) | b2(128)] per code (512B/row, L2-resident)
__device__ __align__(16) __nv_bfloat16 g_B[K_CODES * 256];

// ============================================================
// helpers
// ============================================================
__device__ __forceinline__ uint32_t smem_u32(const void* p) {
    uint32_t a;
    asm("{ .reg .u64 t; cvta.to.shared.u64 t, %1; cvt.u32.u64 %0, t; }" : "=r"(a) : "l"(p));
    return a;
}
__device__ __forceinline__ void ldsm_x4(uint32_t& r0, uint32_t& r1, uint32_t& r2, uint32_t& r3,
                                        uint32_t addr) {
    asm volatile("ldmatrix.sync.aligned.m8n8.x4.shared.b16 {%0,%1,%2,%3}, [%4];"
        : "=r"(r0), "=r"(r1), "=r"(r2), "=r"(r3) : "r"(addr));
}
__device__ __forceinline__ void mma16816(float* c, const uint32_t* a, const uint32_t* b) {
    asm volatile("mma.sync.aligned.m16n8k16.row.col.f32.bf16.bf16.f32 "
        "{%0,%1,%2,%3}, {%4,%5,%6,%7}, {%8,%9}, {%0,%1,%2,%3};"
        : "+f"(c[0]), "+f"(c[1]), "+f"(c[2]), "+f"(c[3])
        : "r"(a[0]), "r"(a[1]), "r"(a[2]), "r"(a[3]), "r"(b[0]), "r"(b[1]));
}
__device__ __forceinline__ uint32_t pack2(float x, float y, uint32_t& lo) {
    __nv_bfloat16 hx = __float2bfloat16(x), hy = __float2bfloat16(y);
    __nv_bfloat16 lx = __float2bfloat16(x - __bfloat162float(hx));
    __nv_bfloat16 ly = __float2bfloat16(y - __bfloat162float(hy));
    lo = (uint32_t)__bfloat16_as_ushort(lx) | ((uint32_t)__bfloat16_as_ushort(ly) << 16);
    return (uint32_t)__bfloat16_as_ushort(hx) | ((uint32_t)__bfloat16_as_ushort(hy) << 16);
}

// ============================================================
// norms (bitwise-matching XLA warp row-reduce) + flag reset
// ============================================================
__device__ __forceinline__ float row_sumsq(const float* __restrict__ src, int w, int lane) {
    float4 v = reinterpret_cast<const float4*>(src + (size_t)w * D_DIM)[lane];
    float s = __fmul_rn(v.x, v.x);
    s = __fadd_rn(s, __fmul_rn(v.y, v.y));
    s = __fadd_rn(s, __fmul_rn(v.z, v.z));
    s = __fadd_rn(s, __fmul_rn(v.w, v.w));
    #pragma unroll
    for (int o = 16; o > 0; o >>= 1)
        s = __fadd_rn(s, __shfl_down_sync(0xffffffffu, s, o));
    return s;
}
__global__ void enorm_kernel(const float* __restrict__ E) {
    if (blockIdx.x == 0 && threadIdx.x == 0) g_flagCount = 0;
    int w = (int)((blockIdx.x * (size_t)blockDim.x + threadIdx.x) >> 5);
    int lane = threadIdx.x & 31;
    if (w >= K_CODES) return;
    float s = row_sumsq(E, w, lane);
    if (lane == 0) g_enorm[w] = s;
}
__global__ void cnorm_kernel(const float* __restrict__ X) {
    int w = (int)((blockIdx.x * (size_t)blockDim.x + threadIdx.x) >> 5);
    int lane = threadIdx.x & 31;
    if (w >= N_ROWS) return;
    float s = row_sumsq(X, w, lane);
    if (lane == 0) g_cnorm[w] = s;
}

// ============================================================
// B' prep: per code n, [b1 | b2], k-contiguous (512B/row)
// ============================================================
__global__ void eprep_kernel(const float* __restrict__ E) {
    int p = blockIdx.x * blockDim.x + threadIdx.x;   // pair id
    if (p >= K_CODES * 64) return;
    int n = p >> 6, cp = (p & 63) * 2;
    float2 v = *reinterpret_cast<const float2*>(E + (size_t)n * D_DIM + cp);
    uint32_t lo, hi = pack2(v.x, v.y, lo);
    uint32_t* row = reinterpret_cast<uint32_t*>(g_B + (size_t)n * 256);
    row[(cp) >> 1]       = hi;
    row[(128 + cp) >> 1] = lo;
}

// ============================================================
// Main mma.sync argmin kernel (v3: B via direct LDG, barrier-free loop).
// 256 thr, 128 rows/CTA, 2 CTAs/SM. smem = A' only (67.6KB).
// warp grid 4(M)x2(N): warp tile 32 rows x 32 codes.
// Per N-tile (64 codes), per ks: ldsm a1 -> mma b1,b2; ldsm a2 -> mma b1.
// B fragments LDG'd straight from L2/L1-cached g_B (no staging, no barriers).
// ============================================================
__global__ void __launch_bounds__(256, 2)
mma_argmin_kernel(const float* __restrict__ X) {
    extern __shared__ char sm[];
    const uint32_t smb = smem_u32(sm);
    const int tid = threadIdx.x;
    const int w = tid >> 5, lane = tid & 31;
    const int wm = w >> 1, wn = w & 1;         // 4 M-groups x 2 N-groups
    const int tg = lane >> 2, tig = lane & 3;
    const int rowBase = blockIdx.x * 128;

    // ---- build A' = [a1 | a2] in smem (256 cols, padded stride) ----
    for (int p = tid; p < 128 * 64; p += 256) {
        int m = p >> 6, cp = (p & 63) * 2;
        float2 v = *reinterpret_cast<const float2*>(X + (size_t)(rowBase + m) * D_DIM + cp);
        uint32_t lo, hi = pack2(v.x, v.y, lo);
        char* rp = sm + (size_t)m * AS_STRIDE_B;
        *reinterpret_cast<uint32_t*>(rp + cp * 2)         = hi;
        *reinterpret_cast<uint32_t*>(rp + (128 + cp) * 2) = lo;
    }

    // per-owned-row |x|^2 : rows wm*32 + mt*16 + tg + h*8
    float cn[2][2];
    #pragma unroll
    for (int mt = 0; mt < 2; ++mt)
        #pragma unroll
        for (int h = 0; h < 2; ++h)
            cn[mt][h] = g_cnorm[rowBase + wm * 32 + mt * 16 + tg + h * 8];

    float m1[2][2], m2[2][2];
    int   i1[2][2];
    #pragma unroll
    for (int mt = 0; mt < 2; ++mt)
        #pragma unroll
        for (int h = 0; h < 2; ++h) { m1[mt][h] = 3.4e38f; m2[mt][h] = 3.4e38f; i1[mt][h] = 0; }

    float acc[2][4][4];
    #pragma unroll
    for (int mt = 0; mt < 2; ++mt)
        #pragma unroll
        for (int nt = 0; nt < 4; ++nt)
            #pragma unroll
            for (int q = 0; q < 4; ++q) acc[mt][nt][q] = 0.f;

    __syncthreads();                          // A' visible to all warps (last barrier)

    // per-lane bases
    // A ldsm: row = wm*32 + mt*16 + (lane&15), k-byte = (lane>>4)*16 (+ks*32; a2 +256)
    const uint32_t aBase = smb + (uint32_t)(wm * 32 + (lane & 15)) * AS_STRIDE_B
                         + (uint32_t)(lane >> 4) * 16;
    // B LDG: code n = NT*64 + wn*32 + nt*8 + (lane>>2); k-byte = (lane&3)*4 (+{0,16}; ks*32; b2 +256)
    const char* bBase = reinterpret_cast<const char*>(g_B)
                      + (size_t)(wn * 32 + (lane >> 2)) * 512 + (lane & 3) * 4;

    for (int NT = 0; NT < 16; ++NT) {
        const char* bp = bBase + (size_t)NT * 32768;   // 64 codes * 512B
        #pragma unroll
        for (int ks = 0; ks < 8; ++ks) {
            // B fragments for both splits (registers, reused across a1/a2)
            uint32_t b1[4][2], b2[4][2];
            #pragma unroll
            for (int nt = 0; nt < 4; ++nt) {
                const char* q = bp + nt * 4096 + ks * 32;
                b1[nt][0] = *reinterpret_cast<const uint32_t*>(q);
                b1[nt][1] = *reinterpret_cast<const uint32_t*>(q + 16);
                b2[nt][0] = *reinterpret_cast<const uint32_t*>(q + 256);
                b2[nt][1] = *reinterpret_cast<const uint32_t*>(q + 272);
            }
            uint32_t a[2][4];
            // a1 fragments -> mma vs b1 and b2
            #pragma unroll
            for (int mt = 0; mt < 2; ++mt)
                ldsm_x4(a[mt][0], a[mt][1], a[mt][2], a[mt][3],
                        aBase + (uint32_t)mt * 16 * AS_STRIDE_B + (uint32_t)ks * 32);
            #pragma unroll
            for (int mt = 0; mt < 2; ++mt)
                #pragma unroll
                for (int nt = 0; nt < 4; ++nt) {
                    mma16816(acc[mt][nt], a[mt], b1[nt]);
                    mma16816(acc[mt][nt], a[mt], b2[nt]);
                }
            // a2 fragments -> mma vs b1 (reuse b1 regs)
            #pragma unroll
            for (int mt = 0; mt < 2; ++mt)
                ldsm_x4(a[mt][0], a[mt][1], a[mt][2], a[mt][3],
                        aBase + (uint32_t)mt * 16 * AS_STRIDE_B + (uint32_t)ks * 32 + 256);
            #pragma unroll
            for (int mt = 0; mt < 2; ++mt)
                #pragma unroll
                for (int nt = 0; nt < 4; ++nt)
                    mma16816(acc[mt][nt], a[mt], b1[nt]);
        }

        // ---- epilogue for this 64-code tile ----
        const int kbase = NT * 64 + wn * 32;
        #pragma unroll
        for (int mt = 0; mt < 2; ++mt)
            #pragma unroll
            for (int h = 0; h < 2; ++h) {
                float base = cn[mt][h];
                #pragma unroll
                for (int nt = 0; nt < 4; ++nt)
                    #pragma unroll
                    for (int cc = 0; cc < 2; ++cc) {
                        int kk = kbase + nt * 8 + 2 * tig + cc;
                        float d = fmaf(-2.f, acc[mt][nt][h * 2 + cc], base + g_enorm[kk]);
                        if (d < m1[mt][h]) {
                            m2[mt][h] = m1[mt][h]; m1[mt][h] = d; i1[mt][h] = kk;
                        } else if (d < m2[mt][h]) m2[mt][h] = d;
                    }
            }
        #pragma unroll
        for (int mt = 0; mt < 2; ++mt)
            #pragma unroll
            for (int nt = 0; nt < 4; ++nt)
                #pragma unroll
                for (int q = 0; q < 4; ++q) acc[mt][nt][q] = 0.f;
    }

    // ---- cross-thread merge: 8 contributors per row (reuse A region) ----
    // No index tie-break needed: approx tie => gap==0 < TAU => flagged =>
    // resolved by the exact (tie-correct) fixup.
    __syncthreads();
    float* redM1 = reinterpret_cast<float*>(sm);          // [128][8]
    float* redM2 = redM1 + 1024;
    int*   redI  = reinterpret_cast<int*>(redM2 + 1024);
    #pragma unroll
    for (int mt = 0; mt < 2; ++mt)
        #pragma unroll
        for (int h = 0; h < 2; ++h) {
            int r = wm * 32 + mt * 16 + tg + h * 8;
            int q = wn * 4 + tig;
            redM1[r * 8 + q] = m1[mt][h];
            redM2[r * 8 + q] = m2[mt][h];
            redI [r * 8 + q] = i1[mt][h];
        }
    __syncthreads();

    float dmin = 0.f;
    if (tid < 128) {
        float M1 = redM1[tid * 8], M2 = redM2[tid * 8];
        int   I  = redI[tid * 8];
        #pragma unroll
        for (int q = 1; q < 8; ++q) {
            float a1v = redM1[tid * 8 + q];
            if (a1v < M1) {
                M2 = fminf(M1, redM2[tid * 8 + q]);
                M1 = a1v;
                I  = redI[tid * 8 + q];
            } else {
                M2 = fminf(M2, a1v);
            }
        }
        int row = rowBase + tid;
        g_idx[row] = I;
        if (M2 - M1 < TAU) {
            int f = atomicAdd(&g_flagCount, 1);
            if (f < FLAG_CAP) g_flagRows[f] = row;
        }
        dmin = M1;
    }
    __syncthreads();

    float* rsum = reinterpret_cast<float*>(sm);
    if (tid < 128) rsum[tid] = dmin;
    __syncthreads();
    for (int off = 64; off > 0; off >>= 1) {
        if (tid < off) rsum[tid] += rsum[tid + off];
        __syncthreads();
    }
    if (tid == 0) g_lossPartial[blockIdx.x] = rsum[0];
}

// ============================================================
// exact fixup for flagged (near-tie) rows: bitwise ref pipeline.
// Reduction carries EXPLICIT index tie-break (jnp.argmin first-min).
// ============================================================
__global__ void fixup_kernel(const float* __restrict__ X, const float* __restrict__ E) {
    __shared__ float xs[128];
    __shared__ float rv[256];
    __shared__ int   ri[256];
    int nf = g_flagCount;
    if (nf > FLAG_CAP) nf = FLAG_CAP;
    for (int f = blockIdx.x; f < nf; f += gridDim.x) {
        int row = g_flagRows[f];
        if (threadIdx.x < 128) xs[threadIdx.x] = X[(size_t)row * D_DIM + threadIdx.x];
        __syncthreads();
        float cnv = g_cnorm[row];
        float bv = 3.4e38f;
        int   bi = 0;
        #pragma unroll
        for (int k0 = 0; k0 < 4; ++k0) {
            int k = threadIdx.x * 4 + k0;          // ascending per thread
            const float* er = E + (size_t)k * D_DIM;
            float acc = 0.f;
            for (int d = 0; d < D_DIM; ++d) acc = fmaf(xs[d], er[d], acc);
            float t1 = __fadd_rn(cnv, g_enorm[k]);
            float dd = __fadd_rn(t1, -__fmul_rn(2.0f, acc));
            if (dd < bv) { bv = dd; bi = k; }
        }
        rv[threadIdx.x] = bv;
        ri[threadIdx.x] = bi;
        __syncthreads();
        for (int off = 128; off > 0; off >>= 1) {
            if (threadIdx.x < off) {
                float rvr = rv[threadIdx.x + off];
                int   rir = ri[threadIdx.x + off];
                if (rvr < rv[threadIdx.x] ||
                    (rvr == rv[threadIdx.x] && rir < ri[threadIdx.x])) {
                    rv[threadIdx.x] = rvr;
                    ri[threadIdx.x] = rir;
                }
            }
            __syncthreads();
        }
        if (threadIdx.x == 0) g_idx[row] = ri[0];
        __syncthreads();
    }
}

// ============================================================
// loss = 1.25 * sum(dmin) / (N*D)
// ============================================================
__global__ void loss_kernel(float* __restrict__ out) {
    __shared__ float smr[256];
    float s = 0.f;
    for (int i = threadIdx.x; i < N_ROWS / 128; i += 256) s += g_lossPartial[i];
    smr[threadIdx.x] = s;
    __syncthreads();
    for (int off = 128; off > 0; off >>= 1) {
        if (threadIdx.x < off) smr[threadIdx.x] += smr[threadIdx.x + off];
        __syncthreads();
    }
    if (threadIdx.x == 0)
        out[0] = smr[0] * (1.25f / ((float)N_ROWS * (float)D_DIM));
}

// ============================================================
// writer: quantized_st = fl(c + fl(e[idx]-c)) + one-hot encodings
// ============================================================
__global__ void __launch_bounds__(256)
writer_kernel(const float* __restrict__ X, const float* __restrict__ E,
              float* __restrict__ out) {
    int warp = (int)((blockIdx.x * (size_t)blockDim.x + threadIdx.x) >> 5);
    int lane = threadIdx.x & 31;
    if (warp >= N_ROWS) return;
    int idx = g_idx[warp];

    const float* er = E + (size_t)idx * D_DIM;
    const float* xr = X + (size_t)warp * D_DIM;
    float* q = out + 1 + (size_t)warp * D_DIM;
    #pragma unroll
    for (int i = 0; i < 4; i++) {
        int d = lane + 32 * i;
        float c = xr[d];
        float e = er[d];
        q[d] = __fadd_rn(c, __fadd_rn(e, -c));
    }
    float* enc = out + 1 + (size_t)N_ROWS * D_DIM + (size_t)warp * K_CODES;
    #pragma unroll
    for (int i = 0; i < 32; i++) {
        int k = lane + 32 * i;
        enc[k] = (k == idx) ? 1.0f : 0.0f;
    }
}

// ============================================================
extern "C" void kernel_launch(void* const* d_in, const int* in_sizes, int n_in,
                              void* d_out, int out_size) {
    const float* X = (const float*)d_in[0];
    const float* E = (const float*)d_in[1];
    float* out = (float*)d_out;

    cudaFuncSetAttribute(mma_argmin_kernel,
                         cudaFuncAttributeMaxDynamicSharedMemorySize, SM_TOTAL);

    enorm_kernel<<<K_CODES * 32 / 256, 256>>>(E);
    cnorm_kernel<<<N_ROWS * 32 / 256, 256>>>(X);
    eprep_kernel<<<(K_CODES * 64) / 256, 256>>>(E);
    mma_argmin_kernel<<<N_ROWS / 128, 256, SM_TOTAL>>>(X);
    fixup_kernel<<<256, 256>>>(X, E);
    loss_kernel<<<1, 256>>>(out);
    writer_kernel<<<N_ROWS / 8, 256>>>(X, E, out);
}

// round 14
// speedup vs baseline: 1.4973x; 1.4973x over previous
#include <cuda_runtime.h>
#include <cuda_bf16.h>
#include <cstddef>
#include <cstdint>

#define N_ROWS 131072
#define K_CODES 1024
#define D_DIM 128
#define TAU 2e-3f    // >= 2x worst-case approx gap-error bound (~1e-3)
#define FLAG_CAP 32768

#define AS_STRIDE_B 528               // A row stride bytes (256 bf16 + 16B pad)
#define SM_A_BYTES  (128 * AS_STRIDE_B)          // 67584
#define SM_TOTAL    (SM_A_BYTES + 4096)          // + enorm cache -> 71680, 2 CTAs/SM

// ---- scratch (device-only access) ----
__device__ int   g_idx[N_ROWS];
__device__ __align__(16) float g_enorm[K_CODES];
__device__ float g_cnorm[N_ROWS];
__device__ float g_lossPartial[N_ROWS / 128];
__device__ int   g_flagCount;
__device__ int   g_flagRows[FLAG_CAP];
// B fragment image: [blk(128)][ks(8)][lane(32)] uint4 = {b1w0,b1w1,b2w0,b2w1}
// blk = 8-code group. One warp LDG.128 = 512B contiguous = full mma B frag, both splits.
__device__ __align__(16) uint4 g_Bf[K_CODES / 8 * 8 * 32];

// ============================================================
// helpers
// ============================================================
__device__ __forceinline__ uint32_t smem_u32(const void* p) {
    uint32_t a;
    asm("{ .reg .u64 t; cvta.to.shared.u64 t, %1; cvt.u32.u64 %0, t; }" : "=r"(a) : "l"(p));
    return a;
}
__device__ __forceinline__ void ldsm_x4(uint32_t& r0, uint32_t& r1, uint32_t& r2, uint32_t& r3,
                                        uint32_t addr) {
    asm volatile("ldmatrix.sync.aligned.m8n8.x4.shared.b16 {%0,%1,%2,%3}, [%4];"
        : "=r"(r0), "=r"(r1), "=r"(r2), "=r"(r3) : "r"(addr));
}
__device__ __forceinline__ void mma16816(float* c, const uint32_t* a, const uint32_t* b) {
    asm volatile("mma.sync.aligned.m16n8k16.row.col.f32.bf16.bf16.f32 "
        "{%0,%1,%2,%3}, {%4,%5,%6,%7}, {%8,%9}, {%0,%1,%2,%3};"
        : "+f"(c[0]), "+f"(c[1]), "+f"(c[2]), "+f"(c[3])
        : "r"(a[0]), "r"(a[1]), "r"(a[2]), "r"(a[3]), "r"(b[0]), "r"(b[1]));
}
__device__ __forceinline__ uint32_t pack2(float x, float y, uint32_t& lo) {
    __nv_bfloat16 hx = __float2bfloat16(x), hy = __float2bfloat16(y);
    __nv_bfloat16 lx = __float2bfloat16(x - __bfloat162float(hx));
    __nv_bfloat16 ly = __float2bfloat16(y - __bfloat162float(hy));
    lo = (uint32_t)__bfloat16_as_ushort(lx) | ((uint32_t)__bfloat16_as_ushort(ly) << 16);
    return (uint32_t)__bfloat16_as_ushort(hx) | ((uint32_t)__bfloat16_as_ushort(hy) << 16);
}

// ============================================================
// norms (bitwise-matching XLA warp row-reduce) + flag reset
// ============================================================
__device__ __forceinline__ float row_sumsq(const float* __restrict__ src, int w, int lane) {
    float4 v = reinterpret_cast<const float4*>(src + (size_t)w * D_DIM)[lane];
    float s = __fmul_rn(v.x, v.x);
    s = __fadd_rn(s, __fmul_rn(v.y, v.y));
    s = __fadd_rn(s, __fmul_rn(v.z, v.z));
    s = __fadd_rn(s, __fmul_rn(v.w, v.w));
    #pragma unroll
    for (int o = 16; o > 0; o >>= 1)
        s = __fadd_rn(s, __shfl_down_sync(0xffffffffu, s, o));
    return s;
}
__global__ void enorm_kernel(const float* __restrict__ E) {
    if (blockIdx.x == 0 && threadIdx.x == 0) g_flagCount = 0;
    int w = (int)((blockIdx.x * (size_t)blockDim.x + threadIdx.x) >> 5);
    int lane = threadIdx.x & 31;
    if (w >= K_CODES) return;
    float s = row_sumsq(E, w, lane);
    if (lane == 0) g_enorm[w] = s;
}
__global__ void cnorm_kernel(const float* __restrict__ X) {
    int w = (int)((blockIdx.x * (size_t)blockDim.x + threadIdx.x) >> 5);
    int lane = threadIdx.x & 31;
    if (w >= N_ROWS) return;
    float s = row_sumsq(X, w, lane);
    if (lane == 0) g_cnorm[w] = s;
}

// ============================================================
// B fragment prep: one thread per (blk, ks, lane).
// Per-lane mapping verified by R13's passing run:
//   code n = blk*8 + (lane>>2); k0 = ks*16 + (lane&3)*2
//   w0 = {k0,k0+1}, w1 = {k0+8,k0+9}; b1 = hi split, b2 = lo split.
// ============================================================
__global__ void eprep_kernel(const float* __restrict__ E) {
    int idx = blockIdx.x * blockDim.x + threadIdx.x;     // 0..32767
    int blk = idx >> 8, ks = (idx >> 5) & 7, lane = idx & 31;
    int n = blk * 8 + (lane >> 2);
    int k0 = ks * 16 + (lane & 3) * 2;
    const float* er = E + (size_t)n * D_DIM;
    uint32_t lo0, hi0 = pack2(er[k0],     er[k0 + 1], lo0);
    uint32_t lo1, hi1 = pack2(er[k0 + 8], er[k0 + 9], lo1);
    g_Bf[idx] = make_uint4(hi0, hi1, lo0, lo1);
}

// ============================================================
// Main mma.sync argmin kernel (v5):
// - warp grid 8M x 1N: warp = 16 rows x full 64-code N-tile (A ldsm 1x, no
//   cross-warp A redundancy; a1/a2 loaded once per ks, reused for b1 & b2).
// - B via coalesced LDG.128 of prebuilt fragment images (L1-resident 32KB/tile).
// - barrier-free mainloop; smem = A' (67.6KB) + enorm cache (4KB); 2 CTAs/SM.
// ============================================================
__global__ void __launch_bounds__(256, 2)
mma_argmin_kernel(const float* __restrict__ X) {
    extern __shared__ char sm[];
    const uint32_t smb = smem_u32(sm);
    float* enSm = reinterpret_cast<float*>(sm + SM_A_BYTES);
    const int tid = threadIdx.x;
    const int w = tid >> 5, lane = tid & 31;
    const int tg = lane >> 2, tig = lane & 3;
    const int rowBase = blockIdx.x * 128;

    // ---- build A' = [a1 | a2] in smem (256 cols, padded stride) ----
    for (int p = tid; p < 128 * 64; p += 256) {
        int m = p >> 6, cp = (p & 63) * 2;
        float2 v = *reinterpret_cast<const float2*>(X + (size_t)(rowBase + m) * D_DIM + cp);
        uint32_t lo, hi = pack2(v.x, v.y, lo);
        char* rp = sm + (size_t)m * AS_STRIDE_B;
        *reinterpret_cast<uint32_t*>(rp + cp * 2)         = hi;
        *reinterpret_cast<uint32_t*>(rp + (128 + cp) * 2) = lo;
    }
    // ---- enorm cache ----
    {
        float4* ef = reinterpret_cast<float4*>(enSm);
        const float4* eg = reinterpret_cast<const float4*>(g_enorm);
        if (tid < 256) ef[tid] = eg[tid];
    }

    // per-owned-row |x|^2 : rows w*16 + tg + h*8
    float cn[2];
    #pragma unroll
    for (int h = 0; h < 2; ++h)
        cn[h] = g_cnorm[rowBase + w * 16 + tg + h * 8];

    float m1[2], m2[2];
    int   i1[2];
    #pragma unroll
    for (int h = 0; h < 2; ++h) { m1[h] = 3.4e38f; m2[h] = 3.4e38f; i1[h] = 0; }

    float acc[8][4];
    #pragma unroll
    for (int bl = 0; bl < 8; ++bl)
        #pragma unroll
        for (int q = 0; q < 4; ++q) acc[bl][q] = 0.f;

    __syncthreads();                          // A' + enSm visible (last barrier)

    // A ldsm base: row = w*16 + (lane&15), k-byte = (lane>>4)*16 (+ks*32; a2 +256)
    const uint32_t aBase = smb + (uint32_t)(w * 16 + (lane & 15)) * AS_STRIDE_B
                         + (uint32_t)(lane >> 4) * 16;

    for (int NT = 0; NT < 16; ++NT) {
        const uint4* bp = g_Bf + (size_t)NT * 2048 + lane;   // + bl*256 + ks*32
        #pragma unroll
        for (int ks = 0; ks < 8; ++ks) {
            uint32_t a1[4], a2[4];
            ldsm_x4(a1[0], a1[1], a1[2], a1[3], aBase + (uint32_t)ks * 32);
            ldsm_x4(a2[0], a2[1], a2[2], a2[3], aBase + (uint32_t)ks * 32 + 256);
            #pragma unroll
            for (int bl = 0; bl < 8; ++bl) {
                uint4 f = bp[bl * 256 + ks * 32];
                uint32_t b1[2] = { f.x, f.y };
                uint32_t b2[2] = { f.z, f.w };
                mma16816(acc[bl], a1, b1);
                mma16816(acc[bl], a1, b2);
                mma16816(acc[bl], a2, b1);
            }
        }
        // ---- epilogue for this 64-code tile ----
        const int kbase = NT * 64;
        #pragma unroll
        for (int bl = 0; bl < 8; ++bl)
            #pragma unroll
            for (int h = 0; h < 2; ++h)
                #pragma unroll
                for (int cc = 0; cc < 2; ++cc) {
                    int kk = kbase + bl * 8 + 2 * tig + cc;
                    float d = fmaf(-2.f, acc[bl][h * 2 + cc], cn[h] + enSm[kk]);
                    if (d < m1[h]) { m2[h] = m1[h]; m1[h] = d; i1[h] = kk; }
                    else if (d < m2[h]) m2[h] = d;
                }
        #pragma unroll
        for (int bl = 0; bl < 8; ++bl)
            #pragma unroll
            for (int q = 0; q < 4; ++q) acc[bl][q] = 0.f;
    }

    // ---- cross-thread merge: 4 contributors (tig) per row (reuse A region) ----
    // No index tie-break needed: approx tie => gap==0 < TAU => flagged =>
    // resolved by the exact (tie-correct) fixup.
    __syncthreads();
    float* redM1 = reinterpret_cast<float*>(sm);          // [128][4]
    float* redM2 = redM1 + 512;
    int*   redI  = reinterpret_cast<int*>(redM2 + 512);
    #pragma unroll
    for (int h = 0; h < 2; ++h) {
        int r = w * 16 + tg + h * 8;
        redM1[r * 4 + tig] = m1[h];
        redM2[r * 4 + tig] = m2[h];
        redI [r * 4 + tig] = i1[h];
    }
    __syncthreads();

    float dmin = 0.f;
    if (tid < 128) {
        float M1 = redM1[tid * 4], M2 = redM2[tid * 4];
        int   I  = redI[tid * 4];
        #pragma unroll
        for (int q = 1; q < 4; ++q) {
            float a1v = redM1[tid * 4 + q];
            if (a1v < M1) {
                M2 = fminf(M1, redM2[tid * 4 + q]);
                M1 = a1v;
                I  = redI[tid * 4 + q];
            } else {
                M2 = fminf(M2, a1v);
            }
        }
        int row = rowBase + tid;
        g_idx[row] = I;
        if (M2 - M1 < TAU) {
            int f = atomicAdd(&g_flagCount, 1);
            if (f < FLAG_CAP) g_flagRows[f] = row;
        }
        dmin = M1;
    }
    __syncthreads();

    float* rsum = reinterpret_cast<float*>(sm);
    if (tid < 128) rsum[tid] = dmin;
    __syncthreads();
    for (int off = 64; off > 0; off >>= 1) {
        if (tid < off) rsum[tid] += rsum[tid + off];
        __syncthreads();
    }
    if (tid == 0) g_lossPartial[blockIdx.x] = rsum[0];
}

// ============================================================
// exact fixup for flagged (near-tie) rows: bitwise ref pipeline.
// Reduction carries EXPLICIT index tie-break (jnp.argmin first-min).
// ============================================================
__global__ void fixup_kernel(const float* __restrict__ X, const float* __restrict__ E) {
    __shared__ float xs[128];
    __shared__ float rv[256];
    __shared__ int   ri[256];
    int nf = g_flagCount;
    if (nf > FLAG_CAP) nf = FLAG_CAP;
    for (int f = blockIdx.x; f < nf; f += gridDim.x) {
        int row = g_flagRows[f];
        if (threadIdx.x < 128) xs[threadIdx.x] = X[(size_t)row * D_DIM + threadIdx.x];
        __syncthreads();
        float cnv = g_cnorm[row];
        float bv = 3.4e38f;
        int   bi = 0;
        #pragma unroll
        for (int k0 = 0; k0 < 4; ++k0) {
            int k = threadIdx.x * 4 + k0;          // ascending per thread
            const float* er = E + (size_t)k * D_DIM;
            float acc = 0.f;
            for (int d = 0; d < D_DIM; ++d) acc = fmaf(xs[d], er[d], acc);
            float t1 = __fadd_rn(cnv, g_enorm[k]);
            float dd = __fadd_rn(t1, -__fmul_rn(2.0f, acc));
            if (dd < bv) { bv = dd; bi = k; }
        }
        rv[threadIdx.x] = bv;
        ri[threadIdx.x] = bi;
        __syncthreads();
        for (int off = 128; off > 0; off >>= 1) {
            if (threadIdx.x < off) {
                float rvr = rv[threadIdx.x + off];
                int   rir = ri[threadIdx.x + off];
                if (rvr < rv[threadIdx.x] ||
                    (rvr == rv[threadIdx.x] && rir < ri[threadIdx.x])) {
                    rv[threadIdx.x] = rvr;
                    ri[threadIdx.x] = rir;
                }
            }
            __syncthreads();
        }
        if (threadIdx.x == 0) g_idx[row] = ri[0];
        __syncthreads();
    }
}

// ============================================================
// loss = 1.25 * sum(dmin) / (N*D)
// ============================================================
__global__ void loss_kernel(float* __restrict__ out) {
    __shared__ float smr[256];
    float s = 0.f;
    for (int i = threadIdx.x; i < N_ROWS / 128; i += 256) s += g_lossPartial[i];
    smr[threadIdx.x] = s;
    __syncthreads();
    for (int off = 128; off > 0; off >>= 1) {
        if (threadIdx.x < off) smr[threadIdx.x] += smr[threadIdx.x + off];
        __syncthreads();
    }
    if (threadIdx.x == 0)
        out[0] = smr[0] * (1.25f / ((float)N_ROWS * (float)D_DIM));
}

// ============================================================
// writer: quantized_st = fl(c + fl(e[idx]-c)) + one-hot encodings
// ============================================================
__global__ void __launch_bounds__(256)
writer_kernel(const float* __restrict__ X, const float* __restrict__ E,
              float* __restrict__ out) {
    int warp = (int)((blockIdx.x * (size_t)blockDim.x + threadIdx.x) >> 5);
    int lane = threadIdx.x & 31;
    if (warp >= N_ROWS) return;
    int idx = g_idx[warp];

    const float* er = E + (size_t)idx * D_DIM;
    const float* xr = X + (size_t)warp * D_DIM;
    float* q = out + 1 + (size_t)warp * D_DIM;
    #pragma unroll
    for (int i = 0; i < 4; i++) {
        int d = lane + 32 * i;
        float c = xr[d];
        float e = er[d];
        q[d] = __fadd_rn(c, __fadd_rn(e, -c));
    }
    float* enc = out + 1 + (size_t)N_ROWS * D_DIM + (size_t)warp * K_CODES;
    #pragma unroll
    for (int i = 0; i < 32; i++) {
        int k = lane + 32 * i;
        enc[k] = (k == idx) ? 1.0f : 0.0f;
    }
}

// ============================================================
extern "C" void kernel_launch(void* const* d_in, const int* in_sizes, int n_in,
                              void* d_out, int out_size) {
    const float* X = (const float*)d_in[0];
    const float* E = (const float*)d_in[1];
    float* out = (float*)d_out;

    cudaFuncSetAttribute(mma_argmin_kernel,
                         cudaFuncAttributeMaxDynamicSharedMemorySize, SM_TOTAL);

    enorm_kernel<<<K_CODES * 32 / 256, 256>>>(E);
    cnorm_kernel<<<N_ROWS * 32 / 256, 256>>>(X);
    eprep_kernel<<<128, 256>>>(E);
    mma_argmin_kernel<<<N_ROWS / 128, 256, SM_TOTAL>>>(X);
    fixup_kernel<<<256, 256>>>(X, E);
    loss_kernel<<<1, 256>>>(out);
    writer_kernel<<<N_ROWS / 8, 256>>>(X, E, out);
}